// round 2
// baseline (speedup 1.0000x reference)
#include <cuda_runtime.h>
#include <cuda_bf16.h>
#include <cstdint>

// FPQuantizer: per-row absmax clip is the identity, so the reference reduces
// to a pure elementwise flex-fp8 quantizer:
//   bias = 7.15625 (exact bf16)
//   L    = max(floor(log2|x| + bias), 1)
//   s    = 2^(L-12) * 2^(-0.15625)
//   out  = rint(x / s) * s
// Transcendental-free via exponent-field bit tricks:
//   floor(log2|x| + 7.15625) = e + 7 + (mant >= 2^0.84375)
//
// R2: 4x float4 per thread, front-batched loads (MLP=4/thread) + streaming
// cache hints (.cs) — pure streaming, no reuse, keep L2 out of the way.

#define QT_THRESH 1.79470907f   // 2^0.84375, fp32-rounded
#define QT_C      0.89735454f   // 2^(-0.15625)
#define QT_CINV   1.11438674f   // 2^(+0.15625)

__device__ __forceinline__ float fpq_quantize(float x) {
    uint32_t b = __float_as_uint(x) & 0x7fffffffu;
    int e = (int)(b >> 23) - 127;
    float mant = __uint_as_float((b & 0x7fffffu) | 0x3f800000u);
    int L = e + 7 + (mant >= QT_THRESH ? 1 : 0);
    L = (L < 1) ? 1 : L;                       // x==0 -> L clamped to 1 -> out 0. Matches ref.
    int k = L - 12;
    float p    = __uint_as_float((uint32_t)(k + 127) << 23);
    float pinv = __uint_as_float((uint32_t)(127 - k) << 23);
    return rintf(x * (pinv * QT_CINV)) * (p * QT_C);  // round-half-even == jnp.round
}

__device__ __forceinline__ float4 fpq_quantize4(float4 v) {
    float4 q;
    q.x = fpq_quantize(v.x);
    q.y = fpq_quantize(v.y);
    q.z = fpq_quantize(v.z);
    q.w = fpq_quantize(v.w);
    return q;
}

// Each thread: 4 float4 = 64 bytes, loads front-batched for MLP.
__global__ __launch_bounds__(256) void FPQuantizer_76312978915927_kernel(
    const float4* __restrict__ x, float4* __restrict__ out, int n4)
{
    int base = (blockIdx.x * blockDim.x + threadIdx.x) * 4;
    if (base + 3 < n4) {
        // front-batch all 4 independent loads (streaming, evict-first)
        float4 v0 = __ldcs(x + base + 0);
        float4 v1 = __ldcs(x + base + 1);
        float4 v2 = __ldcs(x + base + 2);
        float4 v3 = __ldcs(x + base + 3);
        __stcs(out + base + 0, fpq_quantize4(v0));
        __stcs(out + base + 1, fpq_quantize4(v1));
        __stcs(out + base + 2, fpq_quantize4(v2));
        __stcs(out + base + 3, fpq_quantize4(v3));
    } else {
        // ragged tail (not hit for 8192x8192, defensive)
        for (int i = base; i < n4; ++i) {
            __stcs(out + i, fpq_quantize4(__ldcs(x + i)));
        }
    }
}

// Scalar tail kernel (defensive; n divisible by 16 here so it won't launch)
__global__ void FPQuantizer_tail_kernel(const float* __restrict__ x,
                                        float* __restrict__ out,
                                        int start, int n)
{
    int i = start + blockIdx.x * blockDim.x + threadIdx.x;
    if (i < n) out[i] = fpq_quantize(x[i]);
}

extern "C" void kernel_launch(void* const* d_in, const int* in_sizes, int n_in,
                              void* d_out, int out_size)
{
    const float* x = (const float*)d_in[0];
    float* out = (float*)d_out;

    int n = out_size;
    int n4 = n >> 2;                 // number of float4 elements
    const int threads = 256;
    const int per_block = threads * 4;   // float4s per block

    if (n4 > 0) {
        int blocks = (n4 + per_block - 1) / per_block;
        FPQuantizer_76312978915927_kernel<<<blocks, threads>>>(
            (const float4*)x, (float4*)out, n4);
    }
    int tail_start = n4 << 2;
    int tail = n - tail_start;
    if (tail > 0) {
        FPQuantizer_tail_kernel<<<1, 128>>>(x, out, tail_start, n);
    }
}

// round 3
// speedup vs baseline: 1.1028x; 1.1028x over previous
#include <cuda_runtime.h>
#include <cuda_bf16.h>
#include <cstdint>

// FPQuantizer: per-row absmax clip is the identity, so the reference reduces
// to a pure elementwise flex-fp8 quantizer:
//   bias = 7.15625 (exact bf16)
//   L    = max(floor(log2|x| + bias), 1)
//   s    = 2^(L-12) * 2^(-0.15625)
//   out  = rint(x / s) * s
// Transcendental-free via exponent-field bit tricks:
//   floor(log2|x| + 7.15625) = e + 7 + (mant >= 2^0.84375)
//
// R3: 4x float4 per thread with BLOCK-STRIDED addressing (lane-contiguous,
// fully coalesced LDG.128/STG.128: 512B per warp per instruction) + loads
// front-batched for MLP=4. R2's per-thread-contiguous layout broke coalescing
// (L1 72%, L2 64%) — this keeps R1's coalescing AND adds MLP.

#define QT_THRESH 1.79470907f   // 2^0.84375, fp32-rounded
#define QT_C      0.89735454f   // 2^(-0.15625)
#define QT_CINV   1.11438674f   // 2^(+0.15625)

__device__ __forceinline__ float fpq_quantize(float x) {
    uint32_t b = __float_as_uint(x) & 0x7fffffffu;
    int e = (int)(b >> 23) - 127;
    float mant = __uint_as_float((b & 0x7fffffu) | 0x3f800000u);
    int L = e + 7 + (mant >= QT_THRESH ? 1 : 0);
    L = (L < 1) ? 1 : L;                       // x==0 -> L clamped to 1 -> out 0. Matches ref.
    int k = L - 12;
    float p    = __uint_as_float((uint32_t)(k + 127) << 23);
    float pinv = __uint_as_float((uint32_t)(127 - k) << 23);
    return rintf(x * (pinv * QT_CINV)) * (p * QT_C);  // round-half-even == jnp.round
}

__device__ __forceinline__ float4 fpq_quantize4(float4 v) {
    float4 q;
    q.x = fpq_quantize(v.x);
    q.y = fpq_quantize(v.y);
    q.z = fpq_quantize(v.z);
    q.w = fpq_quantize(v.w);
    return q;
}

// Block processes 4*blockDim float4s; thread t handles t, t+256, t+512, t+768
// within the block's tile — every load/store instruction is warp-contiguous.
__global__ __launch_bounds__(256) void FPQuantizer_76312978915927_kernel(
    const float4* __restrict__ x, float4* __restrict__ out, int n4)
{
    const int T = 256;
    int base = blockIdx.x * (T * 4) + threadIdx.x;

    if (base + 3 * T < n4) {
        // front-batch 4 independent, fully-coalesced loads (MLP=4)
        float4 v0 = __ldcs(x + base + 0 * T);
        float4 v1 = __ldcs(x + base + 1 * T);
        float4 v2 = __ldcs(x + base + 2 * T);
        float4 v3 = __ldcs(x + base + 3 * T);
        __stcs(out + base + 0 * T, fpq_quantize4(v0));
        __stcs(out + base + 1 * T, fpq_quantize4(v1));
        __stcs(out + base + 2 * T, fpq_quantize4(v2));
        __stcs(out + base + 3 * T, fpq_quantize4(v3));
    } else {
        // ragged tail block (not hit for 8192x8192: 16M float4s / 1024 exact)
        #pragma unroll
        for (int k = 0; k < 4; ++k) {
            int i = base + k * T;
            if (i < n4) __stcs(out + i, fpq_quantize4(__ldcs(x + i)));
        }
    }
}

// Scalar tail kernel (defensive; n divisible by 4 here so it won't launch)
__global__ void FPQuantizer_tail_kernel(const float* __restrict__ x,
                                        float* __restrict__ out,
                                        int start, int n)
{
    int i = start + blockIdx.x * blockDim.x + threadIdx.x;
    if (i < n) out[i] = fpq_quantize(x[i]);
}

extern "C" void kernel_launch(void* const* d_in, const int* in_sizes, int n_in,
                              void* d_out, int out_size)
{
    const float* x = (const float*)d_in[0];
    float* out = (float*)d_out;

    int n = out_size;
    int n4 = n >> 2;                     // number of float4 elements
    const int threads = 256;
    const int per_block = threads * 4;   // float4s per block

    if (n4 > 0) {
        int blocks = (n4 + per_block - 1) / per_block;
        FPQuantizer_76312978915927_kernel<<<blocks, threads>>>(
            (const float4*)x, (float4*)out, n4);
    }
    int tail_start = n4 << 2;
    int tail = n - tail_start;
    if (tail > 0) {
        FPQuantizer_tail_kernel<<<1, 128>>>(x, out, tail_start, n);
    }
}